// round 10
// baseline (speedup 1.0000x reference)
#include <cuda_runtime.h>
#include <cuda_fp16.h>
#include <cstdint>

#define M_TOTAL 2048
#define K_TOTAL 4096
#define N_TOTAL 11008
#define GROUPSZ 128
#define NPACK   (N_TOTAL / 8)   // 1376

// Scratch (__device__ globals: allocation-free rules)
__device__ __half g_X[(size_t)M_TOTAL * K_TOTAL];   // ~16 MB fp16 activations [M][K]

// ---------------------------------------------------------------------------
// Kernel 1: convert x fp32 -> fp16
// ---------------------------------------------------------------------------
__global__ void convert_x_kernel(const float* __restrict__ x) {
    int idx = blockIdx.x * blockDim.x + threadIdx.x;
    if (idx >= M_TOTAL * K_TOTAL / 8) return;
    const float4* xv = (const float4*)x;
    float4 f0 = xv[idx * 2 + 0];
    float4 f1 = xv[idx * 2 + 1];
    __half2 h[4];
    h[0] = __floats2half2_rn(f0.x, f0.y);
    h[1] = __floats2half2_rn(f0.z, f0.w);
    h[2] = __floats2half2_rn(f1.x, f1.y);
    h[3] = __floats2half2_rn(f1.z, f1.w);
    *(uint4*)(&g_X[(size_t)idx * 8]) = *(uint4*)h;
}

// ---------------------------------------------------------------------------
// Kernel 2: fused dequant + GEMM.  out[M,N] = X[M,K] * dequant(Wq)[K,N] + bias
// mma.sync m16n8k16 fp16->fp32.  BM=128 BN=128 BK=64, 8 warps (2Mx4N),
// warp tile 64x32.  A: 3-stage cp.async.  B: packed int4 LDG -> register ->
// dequant -> STS fp16 into stage buffer for chunk kt+2 (latency hidden under
// the MMA block).  One syncthreads per iteration.  Occupancy 2, grid swizzled
// (blockIdx.x = bm fastest -> B tiles reused ~16x from L2 per wave).
// ---------------------------------------------------------------------------
#define BM 128
#define BN 128
#define BK 64
#define STAGES 3
#define LDA_S 72            // halves per A row (144B -> conflict-free ldsm)
#define LDB_S 136           // halves per B row (272B -> conflict-free ldsm.trans)
#define A_SM_BYTES (BM * LDA_S * 2)            // 18432
#define B_SM_BYTES (BK * LDB_S * 2)            // 17408
#define STAGE_BYTES (A_SM_BYTES + B_SM_BYTES)  // 35840
#define SMEM_TOTAL (STAGES * STAGE_BYTES)      // 107520 (x2 CTA = 215KB <= 228KB)
#define KT (K_TOTAL / BK)   // 64

__device__ __forceinline__ uint32_t smem_u32(const void* p) {
    return (uint32_t)__cvta_generic_to_shared(p);
}
__device__ __forceinline__ void cp_async_16(uint32_t saddr, const void* gaddr) {
    asm volatile("cp.async.cg.shared.global [%0], [%1], 16;\n" :: "r"(saddr), "l"(gaddr));
}

__global__ void __launch_bounds__(256, 2) gemm_kernel(const int* __restrict__ qweight,
                                                      const int* __restrict__ qzeros,
                                                      const float* __restrict__ scales,
                                                      const float* __restrict__ bias,
                                                      float* __restrict__ out) {
    extern __shared__ char smem[];

    const int tid  = threadIdx.x;
    const int lane = tid & 31;
    const int warp = tid >> 5;
    const int warp_m = warp & 1;   // 0..1 -> 64 rows
    const int warp_n = warp >> 1;  // 0..3 -> 32 cols
    const int bm = blockIdx.x;     // M tile (16)  -- fastest: wave spans all bm
    const int bn = blockIdx.y;     // N tile (86)

    // A global->smem mapping (coalesced 128B rows)
    const int a_row = tid >> 3;          // 0..31  (+32 per iter, 4 iters)
    const int a_c0  = (tid & 7) * 8;

    // B packed mapping: thread handles 4 words (k = krow+16i), fixed n-octet
    const int np8  = tid & 15;           // word (8 n) within 128-n tile
    const int krow = tid >> 4;           // 0..15
    const int nw   = bn * 16 + np8;      // global packed-word column
    const int n8   = bn * BN + np8 * 8;  // global n of first element

    const __half*    gA  = g_X + (size_t)(bm * BM) * K_TOTAL;
    const uint32_t*  gQW = (const uint32_t*)qweight;
    const uint32_t*  gQZ = (const uint32_t*)qzeros;

    float acc[4][4][4];
#pragma unroll
    for (int i = 0; i < 4; i++)
#pragma unroll
        for (int j = 0; j < 4; j++)
#pragma unroll
            for (int c = 0; c < 4; c++) acc[i][j][c] = 0.f;

#define LOAD_A_STAGE(st, kq) do {                                               \
        const int _k0 = (kq) * BK;                                              \
        __half* _As = (__half*)(smem + (st) * STAGE_BYTES);                     \
        _Pragma("unroll")                                                       \
        for (int _i = 0; _i < 4; _i++) {                                        \
            int _r = a_row + _i * 32;                                           \
            cp_async_16(smem_u32(&_As[_r * LDA_S + a_c0]),                      \
                        gA + (size_t)_r * K_TOTAL + _k0 + a_c0);                \
        }                                                                       \
        asm volatile("cp.async.commit_group;\n" ::);                            \
    } while (0)

    // fetch packed B data for chunk kq into registers
#define FETCH_B(kq, pw, qzv, sv) do {                                           \
        const int _g = (kq) >> 1;  /* BK=64, GROUPSZ=128 */                     \
        _Pragma("unroll")                                                       \
        for (int _i = 0; _i < 4; _i++) {                                        \
            int _k = (kq) * BK + krow + 16 * _i;                                \
            pw[_i] = gQW[(size_t)_k * NPACK + nw];                              \
        }                                                                       \
        qzv = gQZ[(size_t)_g * NPACK + nw];                                     \
        const float4* _s4 = (const float4*)(scales + (size_t)_g * N_TOTAL + n8);\
        sv[0] = _s4[0];                                                         \
        sv[1] = _s4[1];                                                         \
    } while (0)

    // convert registers -> fp16 B stage buffer
#define STORE_B(st, pw, qzv, sv) do {                                           \
        __half* _Bs = (__half*)(smem + (st) * STAGE_BYTES + A_SM_BYTES);        \
        float _s[8] = {sv[0].x, sv[0].y, sv[0].z, sv[0].w,                      \
                       sv[1].x, sv[1].y, sv[1].z, sv[1].w};                     \
        float _z[8];                                                            \
        _Pragma("unroll")                                                       \
        for (int _j = 0; _j < 8; _j++)                                          \
            _z[_j] = (float)((qzv >> (4 * _j)) & 0xF);                          \
        _Pragma("unroll")                                                       \
        for (int _i = 0; _i < 4; _i++) {                                        \
            int _k = krow + 16 * _i;                                            \
            __half _h[8];                                                       \
            _Pragma("unroll")                                                   \
            for (int _j = 0; _j < 8; _j++) {                                    \
                float _wv = (float)((pw[_i] >> (4 * _j)) & 0xF);                \
                _h[_j] = __float2half((_wv - _z[_j]) * _s[_j]);                 \
            }                                                                   \
            *(uint4*)(&_Bs[_k * LDB_S + np8 * 8]) = *(uint4*)_h;                \
        }                                                                       \
    } while (0)

    // ---- prologue: A stages 0,1 in flight; B chunks 0,1 converted ----
    LOAD_A_STAGE(0, 0);
    LOAD_A_STAGE(1, 1);
    {
        uint32_t pw[4]; uint32_t qzv; float4 sv[2];
        FETCH_B(0, pw, qzv, sv);
        STORE_B(0, pw, qzv, sv);
        FETCH_B(1, pw, qzv, sv);
        STORE_B(1, pw, qzv, sv);
    }

    int sc = 0;   // compute stage
    int sl = 2;   // next load stage
    for (int kt = 0; kt < KT; kt++) {
        asm volatile("cp.async.wait_group 1;\n" ::);
        __syncthreads();   // A(kt) ready; B STS for kt visible; stage sl free

        const int knext = (kt + 2 < KT) ? (kt + 2) : kt;   // tail: dead fill

        // issue long-latency loads early; consumed after the MMA block
        uint32_t pw[4]; uint32_t qzv; float4 sv[2];
        FETCH_B(knext, pw, qzv, sv);
        LOAD_A_STAGE(sl, knext);

        const uint32_t a_base = smem_u32(smem + sc * STAGE_BYTES);
        const uint32_t b_base = smem_u32(smem + sc * STAGE_BYTES + A_SM_BYTES);

#pragma unroll
        for (int k16 = 0; k16 < 4; k16++) {
            uint32_t a[4][4];
            uint32_t b[4][2];
#pragma unroll
            for (int mt = 0; mt < 4; mt++) {
                int row = warp_m * 64 + mt * 16 + (lane & 15);
                int col = k16 * 16 + (lane >> 4) * 8;
                uint32_t addr = a_base + (uint32_t)(row * LDA_S + col) * 2u;
                asm volatile("ldmatrix.sync.aligned.m8n8.x4.shared.b16 {%0,%1,%2,%3}, [%4];"
                             : "=r"(a[mt][0]), "=r"(a[mt][1]), "=r"(a[mt][2]), "=r"(a[mt][3])
                             : "r"(addr));
            }
#pragma unroll
            for (int np = 0; np < 2; np++) {
                int row = k16 * 16 + (lane & 15);
                int col = warp_n * 32 + np * 16 + (lane >> 4) * 8;
                uint32_t addr = b_base + (uint32_t)(row * LDB_S + col) * 2u;
                asm volatile("ldmatrix.sync.aligned.m8n8.x4.trans.shared.b16 {%0,%1,%2,%3}, [%4];"
                             : "=r"(b[np * 2][0]), "=r"(b[np * 2][1]),
                               "=r"(b[np * 2 + 1][0]), "=r"(b[np * 2 + 1][1])
                             : "r"(addr));
            }
#pragma unroll
            for (int mt = 0; mt < 4; mt++) {
#pragma unroll
                for (int nt = 0; nt < 4; nt++) {
                    asm volatile(
                        "mma.sync.aligned.m16n8k16.row.col.f32.f16.f16.f32 "
                        "{%0,%1,%2,%3}, {%4,%5,%6,%7}, {%8,%9}, {%0,%1,%2,%3};"
                        : "+f"(acc[mt][nt][0]), "+f"(acc[mt][nt][1]),
                          "+f"(acc[mt][nt][2]), "+f"(acc[mt][nt][3])
                        : "r"(a[mt][0]), "r"(a[mt][1]), "r"(a[mt][2]), "r"(a[mt][3]),
                          "r"(b[nt][0]), "r"(b[nt][1]));
                }
            }
        }

        // dequant + store B for chunk knext into stage sl (no readers until
        // the syncthreads at iteration kt+2)
        STORE_B(sl, pw, qzv, sv);

        sc = (sc + 1 == STAGES) ? 0 : sc + 1;
        sl = (sl + 1 == STAGES) ? 0 : sl + 1;
    }

    // drain outstanding cp.async before smem goes dead
    asm volatile("cp.async.wait_group 0;\n" ::);
    __syncthreads();

    // epilogue: add bias, store fp32
    const int row0 = bm * BM + warp_m * 64 + (lane >> 2);
    const int col0 = bn * BN + warp_n * 32 + (lane & 3) * 2;
#pragma unroll
    for (int mt = 0; mt < 4; mt++) {
#pragma unroll
        for (int nt = 0; nt < 4; nt++) {
            int col = col0 + nt * 8;
            float2 bv = *(const float2*)&bias[col];
            int r0 = row0 + mt * 16;
            float2 v0 = {acc[mt][nt][0] + bv.x, acc[mt][nt][1] + bv.y};
            float2 v1 = {acc[mt][nt][2] + bv.x, acc[mt][nt][3] + bv.y};
            *(float2*)&out[(size_t)r0 * N_TOTAL + col] = v0;
            *(float2*)&out[(size_t)(r0 + 8) * N_TOTAL + col] = v1;
        }
    }
}

// ---------------------------------------------------------------------------
extern "C" void kernel_launch(void* const* d_in, const int* in_sizes, int n_in,
                              void* d_out, int out_size) {
    const float* x       = (const float*)d_in[0];
    const int*   qweight = (const int*)d_in[1];
    const int*   qzeros  = (const int*)d_in[2];
    const float* scales  = (const float*)d_in[3];
    const float* bias    = (const float*)d_in[4];
    float*       out     = (float*)d_out;

    cudaFuncSetAttribute(gemm_kernel,
                         cudaFuncAttributeMaxDynamicSharedMemorySize, SMEM_TOTAL);

    convert_x_kernel<<<(M_TOTAL * K_TOTAL / 8 + 255) / 256, 256>>>(x);
    gemm_kernel<<<dim3(M_TOTAL / BM, N_TOTAL / BN), 256, SMEM_TOTAL>>>(
        qweight, qzeros, scales, bias, out);
}

// round 11
// speedup vs baseline: 1.5955x; 1.5955x over previous
#include <cuda_runtime.h>
#include <cuda_fp16.h>
#include <cstdint>

#define M_TOTAL 2048
#define K_TOTAL 4096
#define N_TOTAL 11008
#define GROUPSZ 128
#define NPACK   (N_TOTAL / 8)   // 1376

// Scratch (__device__ globals: allocation-free rules)
__device__ __half g_W[(size_t)K_TOTAL * N_TOTAL];   // ~90 MB fp16 dequantized W [K][N]
__device__ __half g_X[(size_t)M_TOTAL * K_TOTAL];   // ~16 MB fp16 activations [M][K]

#define CONV_BLOCKS (M_TOTAL * K_TOTAL / 8 / 256)        // 512? -> 1048576/2048? no: /8/256 = 512*... computed below
// M*K/8 = 1,048,576 elements-of-8; /256 threads = 4096 blocks
#define CONV_NBLK 4096
#define DEQ_NBLK  (K_TOTAL * NPACK / 256)                // 22016

// ---------------------------------------------------------------------------
// Kernel 1 (merged prep): convert x fp32->fp16  +  dequant int4->fp16 [K][N]
// Dequant uses the fp16 magic-number path: nib -> (0x6400|nib) = 1024+nib
// exactly; (w+1024)-(z+1024) exact in fp16; scale applied with __hmul2.
// ---------------------------------------------------------------------------
__global__ void prep_kernel(const float* __restrict__ x,
                            const int* __restrict__ qweight,
                            const int* __restrict__ qzeros,
                            const float* __restrict__ scales) {
    const int b = blockIdx.x;
    if (b < CONV_NBLK) {
        // ---- convert x ----
        int idx = b * 256 + threadIdx.x;          // < M*K/8 exactly
        const float4* xv = (const float4*)x;
        float4 f0 = xv[idx * 2 + 0];
        float4 f1 = xv[idx * 2 + 1];
        __half2 h[4];
        h[0] = __floats2half2_rn(f0.x, f0.y);
        h[1] = __floats2half2_rn(f0.z, f0.w);
        h[2] = __floats2half2_rn(f1.x, f1.y);
        h[3] = __floats2half2_rn(f1.z, f1.w);
        *(uint4*)(&g_X[(size_t)idx * 8]) = *(uint4*)h;
    } else {
        // ---- dequant one packed word -> 8 fp16 ----
        int idx = (b - CONV_NBLK) * 256 + threadIdx.x;   // < K*NPACK exactly
        int k  = idx / NPACK;
        int np = idx - k * NPACK;
        int g  = k / GROUPSZ;

        uint32_t qw = ((const uint32_t*)qweight)[idx];
        uint32_t qz = ((const uint32_t*)qzeros)[(size_t)g * NPACK + np];
        const float4* s4 = (const float4*)(scales + (size_t)g * N_TOTAL + np * 8);
        float4 s0 = s4[0];
        float4 s1 = s4[1];
        __half2 sh[4];
        sh[0] = __floats2half2_rn(s0.x, s0.y);
        sh[1] = __floats2half2_rn(s0.z, s0.w);
        sh[2] = __floats2half2_rn(s1.x, s1.y);
        sh[3] = __floats2half2_rn(s1.z, s1.w);

        __half2 r[4];
#pragma unroll
        for (int p = 0; p < 4; p++) {
            uint32_t xw = qw >> (8 * p);
            uint32_t xz = qz >> (8 * p);
            uint32_t tw = 0x64006400u | (xw & 0xFu) | ((xw & 0xF0u) << 12);
            uint32_t tz = 0x64006400u | (xz & 0xFu) | ((xz & 0xF0u) << 12);
            __half2 d = __hsub2(*(__half2*)&tw, *(__half2*)&tz);  // exact ints
            r[p] = __hmul2(d, sh[p]);
        }
        *(uint4*)(&g_W[(size_t)k * N_TOTAL + np * 8]) = *(uint4*)r;
    }
}

// ---------------------------------------------------------------------------
// Kernel 2: GEMM  out[M,N] = X[M,K] * W[K,N] + bias   (R8, proven 540us)
// mma.sync m16n8k16 fp16->fp32.  BM=128 BN=128 BK=64, 8 warps (2Mx4N),
// warp tile 64x32.  3-stage cp.async, one commit per iteration, FORCED
// occupancy 2 (launch_bounds(256,2)).  Grid swizzled: blockIdx.x = bm
// (fastest) so each wave reuses every B tile ~16x from L2.
// ---------------------------------------------------------------------------
#define BM 128
#define BN 128
#define BK 64
#define STAGES 3
#define LDA_S 72            // halves per A row (144B -> conflict-free ldsm)
#define LDB_S 136           // halves per B row (272B -> conflict-free ldsm.trans)
#define A_SM_BYTES (BM * LDA_S * 2)            // 18432
#define B_SM_BYTES (BK * LDB_S * 2)            // 17408
#define STAGE_BYTES (A_SM_BYTES + B_SM_BYTES)  // 35840
#define SMEM_TOTAL (STAGES * STAGE_BYTES)      // 107520 (x2 CTA = 215KB <= 228KB)
#define KT (K_TOTAL / BK)   // 64

__device__ __forceinline__ uint32_t smem_u32(const void* p) {
    return (uint32_t)__cvta_generic_to_shared(p);
}
__device__ __forceinline__ void cp_async_16(uint32_t saddr, const void* gaddr) {
    asm volatile("cp.async.cg.shared.global [%0], [%1], 16;\n" :: "r"(saddr), "l"(gaddr));
}

__global__ void __launch_bounds__(256, 2) gemm_kernel(const float* __restrict__ bias,
                                                      float* __restrict__ out) {
    extern __shared__ char smem[];

    const int tid  = threadIdx.x;
    const int lane = tid & 31;
    const int warp = tid >> 5;
    const int warp_m = warp & 1;   // 0..1 -> 64 rows
    const int warp_n = warp >> 1;  // 0..3 -> 32 cols
    const int bm = blockIdx.x;     // M tile (16)  -- fastest: wave spans all bm
    const int bn = blockIdx.y;     // N tile (86)

    // fully-coalesced global->smem mapping: 256B contiguous per half-warp
    const int a_row = tid >> 3;          // 0..31  (+32 per iter, 4 iters)
    const int a_c0  = (tid & 7) * 8;     // 8 thr x 16B = 128B row
    const int b_row = tid >> 4;          // 0..15  (+16 per iter, 4 iters)
    const int b_c0  = (tid & 15) * 8;    // 16 thr x 16B = 256B row

    const __half* gA = g_X + (size_t)(bm * BM) * K_TOTAL;
    const __half* gB = g_W + (size_t)(bn * BN);

    float acc[4][4][4];
#pragma unroll
    for (int i = 0; i < 4; i++)
#pragma unroll
        for (int j = 0; j < 4; j++)
#pragma unroll
            for (int c = 0; c < 4; c++) acc[i][j][c] = 0.f;

#define LOAD_STAGE(st, kq) do {                                                 \
        const int _k0 = (kq) * BK;                                              \
        __half* _As = (__half*)(smem + (st) * STAGE_BYTES);                     \
        __half* _Bs = (__half*)(smem + (st) * STAGE_BYTES + A_SM_BYTES);        \
        _Pragma("unroll")                                                       \
        for (int _i = 0; _i < 4; _i++) {                                        \
            int _r = a_row + _i * 32;                                           \
            cp_async_16(smem_u32(&_As[_r * LDA_S + a_c0]),                      \
                        gA + (size_t)_r * K_TOTAL + _k0 + a_c0);                \
        }                                                                       \
        _Pragma("unroll")                                                       \
        for (int _i = 0; _i < 4; _i++) {                                        \
            int _r = b_row + _i * 16;                                           \
            cp_async_16(smem_u32(&_Bs[_r * LDB_S + b_c0]),                      \
                        gB + (size_t)(_k0 + _r) * N_TOTAL + b_c0);              \
        }                                                                       \
        asm volatile("cp.async.commit_group;\n" ::);                            \
    } while (0)

    // prologue: stages 0 and 1 in flight
    LOAD_STAGE(0, 0);
    LOAD_STAGE(1, 1);

    int sc = 0;   // compute stage
    int sl = 2;   // next load stage
    for (int kt = 0; kt < KT; kt++) {
        asm volatile("cp.async.wait_group 1;\n" ::);
        __syncthreads();   // all warps done with previous compute stage (= sl)

        // exactly one commit per iteration; tail reloads current chunk into a
        // dead stage (never consumed) to keep group accounting uniform
        {
            const int knext = (kt + 2 < KT) ? (kt + 2) : kt;
            LOAD_STAGE(sl, knext);
        }

        const uint32_t a_base = smem_u32(smem + sc * STAGE_BYTES);
        const uint32_t b_base = smem_u32(smem + sc * STAGE_BYTES + A_SM_BYTES);

#pragma unroll
        for (int k16 = 0; k16 < 4; k16++) {
            uint32_t a[4][4];
            uint32_t b[4][2];
#pragma unroll
            for (int mt = 0; mt < 4; mt++) {
                int row = warp_m * 64 + mt * 16 + (lane & 15);
                int col = k16 * 16 + (lane >> 4) * 8;
                uint32_t addr = a_base + (uint32_t)(row * LDA_S + col) * 2u;
                asm volatile("ldmatrix.sync.aligned.m8n8.x4.shared.b16 {%0,%1,%2,%3}, [%4];"
                             : "=r"(a[mt][0]), "=r"(a[mt][1]), "=r"(a[mt][2]), "=r"(a[mt][3])
                             : "r"(addr));
            }
#pragma unroll
            for (int np = 0; np < 2; np++) {
                int row = k16 * 16 + (lane & 15);
                int col = warp_n * 32 + np * 16 + (lane >> 4) * 8;
                uint32_t addr = b_base + (uint32_t)(row * LDB_S + col) * 2u;
                asm volatile("ldmatrix.sync.aligned.m8n8.x4.trans.shared.b16 {%0,%1,%2,%3}, [%4];"
                             : "=r"(b[np * 2][0]), "=r"(b[np * 2][1]),
                               "=r"(b[np * 2 + 1][0]), "=r"(b[np * 2 + 1][1])
                             : "r"(addr));
            }
#pragma unroll
            for (int mt = 0; mt < 4; mt++) {
#pragma unroll
                for (int nt = 0; nt < 4; nt++) {
                    asm volatile(
                        "mma.sync.aligned.m16n8k16.row.col.f32.f16.f16.f32 "
                        "{%0,%1,%2,%3}, {%4,%5,%6,%7}, {%8,%9}, {%0,%1,%2,%3};"
                        : "+f"(acc[mt][nt][0]), "+f"(acc[mt][nt][1]),
                          "+f"(acc[mt][nt][2]), "+f"(acc[mt][nt][3])
                        : "r"(a[mt][0]), "r"(a[mt][1]), "r"(a[mt][2]), "r"(a[mt][3]),
                          "r"(b[nt][0]), "r"(b[nt][1]));
                }
            }
        }
        sc = (sc + 1 == STAGES) ? 0 : sc + 1;
        sl = (sl + 1 == STAGES) ? 0 : sl + 1;
    }

    // drain outstanding cp.async before smem goes dead
    asm volatile("cp.async.wait_group 0;\n" ::);
    __syncthreads();

    // epilogue: add bias, store fp32
    const int row0 = bm * BM + warp_m * 64 + (lane >> 2);
    const int col0 = bn * BN + warp_n * 32 + (lane & 3) * 2;
#pragma unroll
    for (int mt = 0; mt < 4; mt++) {
#pragma unroll
        for (int nt = 0; nt < 4; nt++) {
            int col = col0 + nt * 8;
            float2 bv = *(const float2*)&bias[col];
            int r0 = row0 + mt * 16;
            float2 v0 = {acc[mt][nt][0] + bv.x, acc[mt][nt][1] + bv.y};
            float2 v1 = {acc[mt][nt][2] + bv.x, acc[mt][nt][3] + bv.y};
            *(float2*)&out[(size_t)r0 * N_TOTAL + col] = v0;
            *(float2*)&out[(size_t)(r0 + 8) * N_TOTAL + col] = v1;
        }
    }
}

// ---------------------------------------------------------------------------
extern "C" void kernel_launch(void* const* d_in, const int* in_sizes, int n_in,
                              void* d_out, int out_size) {
    const float* x       = (const float*)d_in[0];
    const int*   qweight = (const int*)d_in[1];
    const int*   qzeros  = (const int*)d_in[2];
    const float* scales  = (const float*)d_in[3];
    const float* bias    = (const float*)d_in[4];
    float*       out     = (float*)d_out;

    cudaFuncSetAttribute(gemm_kernel,
                         cudaFuncAttributeMaxDynamicSharedMemorySize, SMEM_TOTAL);

    prep_kernel<<<CONV_NBLK + DEQ_NBLK, 256>>>(x, qweight, qzeros, scales);
    gemm_kernel<<<dim3(M_TOTAL / BM, N_TOTAL / BN), 256, SMEM_TOTAL>>>(bias, out);
}